// round 13
// baseline (speedup 1.0000x reference)
#include <cuda_runtime.h>
#include <cuda_fp16.h>
#include <cstdint>

// Problem constants
#define BATCH 16
#define NN    1024
#define FF    128
#define GTOT  (BATCH * NN)     // 16384

// ---------------------------------------------------------------------------
// Device-global scratch (no allocations allowed)
// ---------------------------------------------------------------------------
__device__ float  g_dinv[GTOT];             // 64 KB
__device__ __half g_Ah[(size_t)GTOT * NN];  // 32 MB  (A, diag patched to A+1) fp16
__device__ __half g_YsT_h[FF * GTOT];       // 4 MB   [f][g] fp16, d_m-scaled

// ---------------------------------------------------------------------------
// Helpers
// ---------------------------------------------------------------------------
__device__ __forceinline__ uint32_t smem_to_u32(const void* p) {
    uint32_t a;
    asm("{ .reg .u64 t; cvta.to.shared.u64 t, %1; cvt.u32.u64 %0, t; }" : "=r"(a) : "l"(p));
    return a;
}
#define CP_ASYNC_16(dst_u32, src) \
    asm volatile("cp.async.cg.shared.global [%0], [%1], 16;" \
                 :: "r"(dst_u32), "l"(src) : "memory")
#define CP_ASYNC_COMMIT()  asm volatile("cp.async.commit_group;" ::: "memory")
#define CP_ASYNC_WAIT1()   asm volatile("cp.async.wait_group 1;" ::: "memory")
#define CP_ASYNC_WAIT0()   asm volatile("cp.async.wait_group 0;" ::: "memory")

#define LDSM_X4(r0, r1, r2, r3, addr) \
    asm volatile("ldmatrix.sync.aligned.m8n8.x4.shared.b16 {%0,%1,%2,%3}, [%4];" \
                 : "=r"(r0), "=r"(r1), "=r"(r2), "=r"(r3) : "r"(addr))

__device__ __forceinline__ void mma_f16(float* c, const uint32_t* a, const uint32_t* b) {
    asm volatile(
        "mma.sync.aligned.m16n8k16.row.col.f32.f16.f16.f32 "
        "{%0,%1,%2,%3}, {%4,%5,%6,%7}, {%8,%9}, {%0,%1,%2,%3};\n"
        : "+f"(c[0]), "+f"(c[1]), "+f"(c[2]), "+f"(c[3])
        : "r"(a[0]), "r"(a[1]), "r"(a[2]), "r"(a[3]), "r"(b[0]), "r"(b[1]));
}
__device__ __forceinline__ uint32_t pack_h2(float x, float y) {
    __half2 h = __floats2half2_rn(x, y);
    return reinterpret_cast<uint32_t&>(h);
}

// ---------------------------------------------------------------------------
// Kernel 0: zero the output (mma accumulates into it with atomics)
// ---------------------------------------------------------------------------
__global__ void __launch_bounds__(256) zero_out(float* __restrict__ out) {
    const size_t i = ((size_t)blockIdx.x * 256 + threadIdx.x) * 4;
    *reinterpret_cast<float4*>(out + i) = make_float4(0.f, 0.f, 0.f, 0.f);
}

// ---------------------------------------------------------------------------
// Kernel 1: dinv[row] = rsqrt(rowsum(A)+1)  AND  g_Ah = fp16(A)
//   (R11 version — dense 16B-stride loads, measured 14.9 us)
// ---------------------------------------------------------------------------
__global__ void __launch_bounds__(256) deg_kernel(const float* __restrict__ A) {
    const int wid = threadIdx.x >> 5, lid = threadIdx.x & 31;
    const int row0 = blockIdx.x * 16 + wid * 2;
    const float4* r0 = reinterpret_cast<const float4*>(A + (size_t)row0 * NN);
    const float4* r1 = reinterpret_cast<const float4*>(A + (size_t)(row0 + 1) * NN);
    __half* h0 = g_Ah + (size_t)row0 * NN;
    __half* h1 = h0 + NN;
    float s0 = 0.f, s1 = 0.f;
    #pragma unroll
    for (int i = 0; i < 8; i++) {
        float4 a = r0[lid + i * 32];
        float4 b = r1[lid + i * 32];
        s0 += (a.x + a.y) + (a.z + a.w);
        s1 += (b.x + b.y) + (b.z + b.w);
        uint2 pa = make_uint2(pack_h2(a.x, a.y), pack_h2(a.z, a.w));
        uint2 pb = make_uint2(pack_h2(b.x, b.y), pack_h2(b.z, b.w));
        *reinterpret_cast<uint2*>(h0 + (lid + i * 32) * 4) = pa;
        *reinterpret_cast<uint2*>(h1 + (lid + i * 32) * 4) = pb;
    }
    #pragma unroll
    for (int o = 16; o; o >>= 1) {
        s0 += __shfl_xor_sync(0xFFFFFFFFu, s0, o);
        s1 += __shfl_xor_sync(0xFFFFFFFFu, s1, o);
    }
    if (lid == 0) {
        g_dinv[row0]     = rsqrtf(s0 + 1.0f);
        g_dinv[row0 + 1] = rsqrtf(s1 + 1.0f);
    }
}

// ---------------------------------------------------------------------------
// Kernel 2: YsT_h[f][g] = fp16( d_m * (X @ W) )  via fp16 mma.sync,
//   PLUS diagonal patch: g_Ah[g][g%N] = fp16(A[g][g%N] + 1).
// ---------------------------------------------------------------------------
#define P2 272
#define XS_SZ (128 * P2)
#define SMEM2 (2 * XS_SZ)

__global__ void __launch_bounds__(256) gemm_xw_t(const float* __restrict__ X,
                                                 const float* __restrict__ W,
                                                 const float* __restrict__ A) {
    extern __shared__ char sm2[];
    char* Xs = sm2;
    char* Ws = sm2 + XS_SZ;

    const int tid = threadIdx.x;
    const int wid = tid >> 5, lane = tid & 31;
    const int g = lane >> 2, tig = lane & 3;
    const int wm = wid & 1, wn = wid >> 1;
    const int m0g = blockIdx.x * 128;

    // Diagonal patch for this block's 128 rows (A+I folded into Ah)
    if (tid < 128) {
        const int gr = m0g + tid;
        const int dc = gr & (NN - 1);
        const size_t idx = (size_t)gr * NN + dc;
        g_Ah[idx] = __float2half_rn(A[idx] + 1.0f);
    }

    for (int idx = tid; idx < 128 * 128; idx += 256) {
        int k = idx >> 7, f = idx & 127;
        float w = W[idx];
        *reinterpret_cast<__half*>(Ws + f * P2 + k * 2) = __float2half_rn(w);
    }
    {
        const int r = tid >> 1, half = tid & 1;
        const float* xp = X + (size_t)(m0g + r) * FF + half * 64;
        char* dst = Xs + r * P2 + half * 128;
        #pragma unroll
        for (int j = 0; j < 8; j++) {
            float4 v0 = *reinterpret_cast<const float4*>(xp + j * 8);
            float4 v1 = *reinterpret_cast<const float4*>(xp + j * 8 + 4);
            uint4 o;
            o.x = pack_h2(v0.x, v0.y); o.y = pack_h2(v0.z, v0.w);
            o.z = pack_h2(v1.x, v1.y); o.w = pack_h2(v1.z, v1.w);
            *reinterpret_cast<uint4*>(dst + j * 16) = o;
        }
    }
    __syncthreads();

    float acc[4][4][4];
    #pragma unroll
    for (int i = 0; i < 4; i++)
        #pragma unroll
        for (int j = 0; j < 4; j++)
            #pragma unroll
            for (int k = 0; k < 4; k++) acc[i][j][k] = 0.f;

    #pragma unroll
    for (int ks = 0; ks < 8; ks++) {
        const int kb = ks * 32 + tig * 4;
        uint32_t af[4][4], bf2[4][2];
        #pragma unroll
        for (int mt = 0; mt < 4; mt++) {
            char* p = Xs + (wm * 64 + mt * 16 + g) * P2 + kb;
            af[mt][0] = *reinterpret_cast<uint32_t*>(p);
            af[mt][1] = *reinterpret_cast<uint32_t*>(p + 8 * P2);
            af[mt][2] = *reinterpret_cast<uint32_t*>(p + 16);
            af[mt][3] = *reinterpret_cast<uint32_t*>(p + 8 * P2 + 16);
        }
        #pragma unroll
        for (int nt = 0; nt < 4; nt++) {
            char* p = Ws + (wn * 32 + nt * 8 + g) * P2 + kb;
            bf2[nt][0] = *reinterpret_cast<uint32_t*>(p);
            bf2[nt][1] = *reinterpret_cast<uint32_t*>(p + 16);
        }
        #pragma unroll
        for (int mt = 0; mt < 4; mt++)
            #pragma unroll
            for (int nt = 0; nt < 4; nt++)
                mma_f16(acc[mt][nt], af[mt], bf2[nt]);
    }
    __syncthreads();

    // Stage transposed fp16 output Os[f][g] for coalesced YsT_h writes
    char* Os = Xs;
    #pragma unroll
    for (int mt = 0; mt < 4; mt++) {
        const int gl0 = wm * 64 + mt * 16 + g;
        const int gg0 = m0g + gl0;
        const float d0 = g_dinv[gg0];
        const float d1 = g_dinv[gg0 + 8];
        #pragma unroll
        for (int nt = 0; nt < 4; nt++) {
            const int f = wn * 32 + nt * 8 + tig * 2;
            float c0 = acc[mt][nt][0] * d0, c1 = acc[mt][nt][1] * d0;
            float c2 = acc[mt][nt][2] * d1, c3 = acc[mt][nt][3] * d1;
            *reinterpret_cast<__half*>(Os + f * P2 + gl0 * 2)             = __float2half_rn(c0);
            *reinterpret_cast<__half*>(Os + (f + 1) * P2 + gl0 * 2)       = __float2half_rn(c1);
            *reinterpret_cast<__half*>(Os + f * P2 + (gl0 + 8) * 2)       = __float2half_rn(c2);
            *reinterpret_cast<__half*>(Os + (f + 1) * P2 + (gl0 + 8) * 2) = __float2half_rn(c3);
        }
    }
    __syncthreads();
    {
        const int f = tid >> 1, half = tid & 1;
        char* src = Os + f * P2 + half * 128;
        __half* dst = g_YsT_h + (size_t)f * GTOT + m0g + half * 64;
        #pragma unroll
        for (int j = 0; j < 8; j++)
            *reinterpret_cast<uint4*>(dst + j * 8) = *reinterpret_cast<uint4*>(src + j * 16);
    }
}

// ---------------------------------------------------------------------------
// Kernel 3: out += d_n * ( (A+I)[b,n,k0:k0+256] @ Ysd[b][k0:k0+256,:] )
//   4-way K-split: grid (8, 16, 4) = 512 CTAs, 3 CTAs/SM co-resident.
//   CTA 128x128, K-chunk 64, 2-stage cp.async (double sync per chunk),
//   ldmatrix + fp16 mma.sync.  Partials via atomicAdd onto zeroed output.
// ---------------------------------------------------------------------------
#define PA3 144                     // 64 fp16 = 128B + 16B pad
#define TA3 (128 * PA3)             // 18432
#define STG3 (2 * TA3)              // 36864 (A + B per stage)
#define NSTAGE 2
#define SMEM3 (NSTAGE * STG3)       // 73728 (x3 CTAs = 221 KB/SM)
#define KSPLIT 4
#define NCHUNK (NN / KSPLIT / 64)   // 4

__global__ void __launch_bounds__(256, 3) gemm_mma(float* __restrict__ out) {
    extern __shared__ char sm[];
    const uint32_t sb = smem_to_u32(sm);

    const int tid = threadIdx.x;
    const int wid = tid >> 5, lane = tid & 31;
    const int g = lane >> 2, tig = lane & 3;
    const int wm = wid & 1, wn = wid >> 1;
    const int b = blockIdx.y;
    const int rowStart = blockIdx.x * 128;
    const int k0 = blockIdx.z * (NN / KSPLIT);   // 0, 256, 512, 768

    // cp.async mapping: row = tid>>1, half = tid&1 (32 of 64 k-values, 64B)
    const int cr = tid >> 1;
    const int ch = tid & 1;
    const __half* Ap = g_Ah + ((size_t)b * NN + rowStart + cr) * NN + k0 + ch * 32;
    const __half* Bp = g_YsT_h + (size_t)cr * GTOT + (size_t)b * NN + k0 + ch * 32;
    const uint32_t dA0 = sb + cr * PA3 + ch * 64;
    const uint32_t dB0 = dA0 + TA3;

    auto issue = [&](int kc) {
        const uint32_t s = (kc & 1) * STG3;
        const __half* pa = Ap + kc * 64;
        const __half* pb = Bp + kc * 64;
        #pragma unroll
        for (int j = 0; j < 4; j++) CP_ASYNC_16(dA0 + s + j * 16, pa + j * 8);
        #pragma unroll
        for (int j = 0; j < 4; j++) CP_ASYNC_16(dB0 + s + j * 16, pb + j * 8);
        CP_ASYNC_COMMIT();
    };

    // ldmatrix lane addressing
    const int t = lane >> 3, r8 = lane & 7;
    const uint32_t aOff = (uint32_t)(wm * 64 + (t & 1) * 8 + r8) * PA3 + ((t >> 1) * 8) * 2;
    const uint32_t bOff = TA3 + (uint32_t)(wn * 32 + (t >> 1) * 8 + r8) * PA3 + ((t & 1) * 8) * 2;

    float acc[4][4][4];
    #pragma unroll
    for (int i = 0; i < 4; i++)
        #pragma unroll
        for (int j = 0; j < 4; j++)
            #pragma unroll
            for (int k = 0; k < 4; k++) acc[i][j][k] = 0.f;

    issue(0);

    for (int kc = 0; kc < NCHUNK; kc++) {
        if (kc + 1 < NCHUNK) { issue(kc + 1); CP_ASYNC_WAIT1(); }
        else                 { CP_ASYNC_WAIT0(); }
        __syncthreads();

        const uint32_t st = sb + (kc & 1) * STG3;

        #pragma unroll
        for (int ks = 0; ks < 4; ks++) {
            uint32_t af[4][4], bf2[4][2];
            #pragma unroll
            for (int mt = 0; mt < 4; mt++)
                LDSM_X4(af[mt][0], af[mt][1], af[mt][2], af[mt][3],
                        st + aOff + (uint32_t)mt * 16 * PA3 + ks * 32);
            #pragma unroll
            for (int np = 0; np < 2; np++)
                LDSM_X4(bf2[np * 2][0], bf2[np * 2][1], bf2[np * 2 + 1][0], bf2[np * 2 + 1][1],
                        st + bOff + (uint32_t)np * 16 * PA3 + ks * 32);
            #pragma unroll
            for (int mt = 0; mt < 4; mt++)
                #pragma unroll
                for (int nt = 0; nt < 4; nt++)
                    mma_f16(acc[mt][nt], af[mt], bf2[nt]);
        }
        __syncthreads();   // guard: next iteration's issue() reuses this buffer
    }

    // Epilogue: out += d_n * acc   (K-split partial, atomic accumulate)
    #pragma unroll
    for (int mt = 0; mt < 4; mt++) {
        const int gr0 = b * NN + rowStart + wm * 64 + mt * 16 + g;
        const float d0 = g_dinv[gr0];
        const float d1 = g_dinv[gr0 + 8];
        float* o0 = out + (size_t)gr0 * FF + wn * 32 + tig * 2;
        float* o1 = o0 + (size_t)8 * FF;
        #pragma unroll
        for (int nt = 0; nt < 4; nt++) {
            atomicAdd(o0 + nt * 8,     d0 * acc[mt][nt][0]);
            atomicAdd(o0 + nt * 8 + 1, d0 * acc[mt][nt][1]);
            atomicAdd(o1 + nt * 8,     d1 * acc[mt][nt][2]);
            atomicAdd(o1 + nt * 8 + 1, d1 * acc[mt][nt][3]);
        }
    }
}

// ---------------------------------------------------------------------------
// kernel_launch
// ---------------------------------------------------------------------------
extern "C" void kernel_launch(void* const* d_in, const int* in_sizes, int n_in,
                              void* d_out, int out_size) {
    const float* X = (const float*)d_in[0];   // [16,1024,128]
    const float* A = (const float*)d_in[1];   // [16,1024,1024]
    const float* W = (const float*)d_in[2];   // [128,128]
    float* out = (float*)d_out;               // [16,1024,128]

    cudaFuncSetAttribute(gemm_xw_t, cudaFuncAttributeMaxDynamicSharedMemorySize, SMEM2);
    cudaFuncSetAttribute(gemm_mma, cudaFuncAttributeMaxDynamicSharedMemorySize, SMEM3);

    // 0) zero the output (mma atomically accumulates K-split partials)
    zero_out<<<(GTOT * FF) / (256 * 4), 256>>>(out);

    // 1) dinv = rsqrt(rowsum(A)+1)  +  Ah = fp16(A) (fused)
    deg_kernel<<<GTOT / 16, 256>>>(A);

    // 2) YsT_h = fp16(d_m * (X @ W)) transposed  +  Ah diagonal patch (+I)
    gemm_xw_t<<<GTOT / 128, 256, SMEM2>>>(X, W, A);

    // 3) out += d_n * ((A+I) @ Ysd)  via 4-way K-split ldmatrix + fp16 mma.sync
    {
        dim3 grid(NN / 128, BATCH, KSPLIT);
        gemm_mma<<<grid, 256, SMEM3>>>(out);
    }
}

// round 14
// speedup vs baseline: 1.4498x; 1.4498x over previous
#include <cuda_runtime.h>
#include <cuda_fp16.h>
#include <cstdint>

// Problem constants
#define BATCH 16
#define NN    1024
#define FF    128
#define GTOT  (BATCH * NN)     // 16384

// ---------------------------------------------------------------------------
// Device-global scratch (no allocations allowed)
// ---------------------------------------------------------------------------
__device__ float  g_dinv[GTOT];             // 64 KB
__device__ __half g_Ah[(size_t)GTOT * NN];  // 32 MB  (A, diag patched to A+1) fp16
__device__ __half g_YsT_h[FF * GTOT];       // 4 MB   [f][g] fp16, d_m-scaled

// ---------------------------------------------------------------------------
// Helpers
// ---------------------------------------------------------------------------
__device__ __forceinline__ uint32_t smem_to_u32(const void* p) {
    uint32_t a;
    asm("{ .reg .u64 t; cvta.to.shared.u64 t, %1; cvt.u32.u64 %0, t; }" : "=r"(a) : "l"(p));
    return a;
}
#define CP_ASYNC_16(dst_u32, src) \
    asm volatile("cp.async.cg.shared.global [%0], [%1], 16;" \
                 :: "r"(dst_u32), "l"(src) : "memory")
#define CP_ASYNC_COMMIT()  asm volatile("cp.async.commit_group;" ::: "memory")
#define CP_ASYNC_WAIT1()   asm volatile("cp.async.wait_group 1;" ::: "memory")
#define CP_ASYNC_WAIT0()   asm volatile("cp.async.wait_group 0;" ::: "memory")

#define LDSM_X4(r0, r1, r2, r3, addr) \
    asm volatile("ldmatrix.sync.aligned.m8n8.x4.shared.b16 {%0,%1,%2,%3}, [%4];" \
                 : "=r"(r0), "=r"(r1), "=r"(r2), "=r"(r3) : "r"(addr))

__device__ __forceinline__ void mma_f16(float* c, const uint32_t* a, const uint32_t* b) {
    asm volatile(
        "mma.sync.aligned.m16n8k16.row.col.f32.f16.f16.f32 "
        "{%0,%1,%2,%3}, {%4,%5,%6,%7}, {%8,%9}, {%0,%1,%2,%3};\n"
        : "+f"(c[0]), "+f"(c[1]), "+f"(c[2]), "+f"(c[3])
        : "r"(a[0]), "r"(a[1]), "r"(a[2]), "r"(a[3]), "r"(b[0]), "r"(b[1]));
}
__device__ __forceinline__ uint32_t pack_h2(float x, float y) {
    __half2 h = __floats2half2_rn(x, y);
    return reinterpret_cast<uint32_t&>(h);
}

// ---------------------------------------------------------------------------
// Kernel 0: zero the output (mma accumulates into it with atomics)
// ---------------------------------------------------------------------------
__global__ void __launch_bounds__(256) zero_out(float* __restrict__ out) {
    const size_t i = ((size_t)blockIdx.x * 256 + threadIdx.x) * 4;
    *reinterpret_cast<float4*>(out + i) = make_float4(0.f, 0.f, 0.f, 0.f);
}

// ---------------------------------------------------------------------------
// Kernel 1: dinv[row] = rsqrt(rowsum(A)+1)  AND  g_Ah = fp16(A)
//   (R11 version — dense 16B-stride loads, measured 14.9 us)
// ---------------------------------------------------------------------------
__global__ void __launch_bounds__(256) deg_kernel(const float* __restrict__ A) {
    const int wid = threadIdx.x >> 5, lid = threadIdx.x & 31;
    const int row0 = blockIdx.x * 16 + wid * 2;
    const float4* r0 = reinterpret_cast<const float4*>(A + (size_t)row0 * NN);
    const float4* r1 = reinterpret_cast<const float4*>(A + (size_t)(row0 + 1) * NN);
    __half* h0 = g_Ah + (size_t)row0 * NN;
    __half* h1 = h0 + NN;
    float s0 = 0.f, s1 = 0.f;
    #pragma unroll
    for (int i = 0; i < 8; i++) {
        float4 a = r0[lid + i * 32];
        float4 b = r1[lid + i * 32];
        s0 += (a.x + a.y) + (a.z + a.w);
        s1 += (b.x + b.y) + (b.z + b.w);
        uint2 pa = make_uint2(pack_h2(a.x, a.y), pack_h2(a.z, a.w));
        uint2 pb = make_uint2(pack_h2(b.x, b.y), pack_h2(b.z, b.w));
        *reinterpret_cast<uint2*>(h0 + (lid + i * 32) * 4) = pa;
        *reinterpret_cast<uint2*>(h1 + (lid + i * 32) * 4) = pb;
    }
    #pragma unroll
    for (int o = 16; o; o >>= 1) {
        s0 += __shfl_xor_sync(0xFFFFFFFFu, s0, o);
        s1 += __shfl_xor_sync(0xFFFFFFFFu, s1, o);
    }
    if (lid == 0) {
        g_dinv[row0]     = rsqrtf(s0 + 1.0f);
        g_dinv[row0 + 1] = rsqrtf(s1 + 1.0f);
    }
}

// ---------------------------------------------------------------------------
// Kernel 2: YsT_h[f][g] = fp16( d_m * (X @ W) )  via fp16 mma.sync,
//   PLUS diagonal patch: g_Ah[g][g%N] = fp16(A[g][g%N] + 1).
// ---------------------------------------------------------------------------
#define P2 272
#define XS_SZ (128 * P2)
#define SMEM2 (2 * XS_SZ)

__global__ void __launch_bounds__(256) gemm_xw_t(const float* __restrict__ X,
                                                 const float* __restrict__ W,
                                                 const float* __restrict__ A) {
    extern __shared__ char sm2[];
    char* Xs = sm2;
    char* Ws = sm2 + XS_SZ;

    const int tid = threadIdx.x;
    const int wid = tid >> 5, lane = tid & 31;
    const int g = lane >> 2, tig = lane & 3;
    const int wm = wid & 1, wn = wid >> 1;
    const int m0g = blockIdx.x * 128;

    // Diagonal patch for this block's 128 rows (A+I folded into Ah)
    if (tid < 128) {
        const int gr = m0g + tid;
        const int dc = gr & (NN - 1);
        const size_t idx = (size_t)gr * NN + dc;
        g_Ah[idx] = __float2half_rn(A[idx] + 1.0f);
    }

    for (int idx = tid; idx < 128 * 128; idx += 256) {
        int k = idx >> 7, f = idx & 127;
        float w = W[idx];
        *reinterpret_cast<__half*>(Ws + f * P2 + k * 2) = __float2half_rn(w);
    }
    {
        const int r = tid >> 1, half = tid & 1;
        const float* xp = X + (size_t)(m0g + r) * FF + half * 64;
        char* dst = Xs + r * P2 + half * 128;
        #pragma unroll
        for (int j = 0; j < 8; j++) {
            float4 v0 = *reinterpret_cast<const float4*>(xp + j * 8);
            float4 v1 = *reinterpret_cast<const float4*>(xp + j * 8 + 4);
            uint4 o;
            o.x = pack_h2(v0.x, v0.y); o.y = pack_h2(v0.z, v0.w);
            o.z = pack_h2(v1.x, v1.y); o.w = pack_h2(v1.z, v1.w);
            *reinterpret_cast<uint4*>(dst + j * 16) = o;
        }
    }
    __syncthreads();

    float acc[4][4][4];
    #pragma unroll
    for (int i = 0; i < 4; i++)
        #pragma unroll
        for (int j = 0; j < 4; j++)
            #pragma unroll
            for (int k = 0; k < 4; k++) acc[i][j][k] = 0.f;

    #pragma unroll
    for (int ks = 0; ks < 8; ks++) {
        const int kb = ks * 32 + tig * 4;
        uint32_t af[4][4], bf2[4][2];
        #pragma unroll
        for (int mt = 0; mt < 4; mt++) {
            char* p = Xs + (wm * 64 + mt * 16 + g) * P2 + kb;
            af[mt][0] = *reinterpret_cast<uint32_t*>(p);
            af[mt][1] = *reinterpret_cast<uint32_t*>(p + 8 * P2);
            af[mt][2] = *reinterpret_cast<uint32_t*>(p + 16);
            af[mt][3] = *reinterpret_cast<uint32_t*>(p + 8 * P2 + 16);
        }
        #pragma unroll
        for (int nt = 0; nt < 4; nt++) {
            char* p = Ws + (wn * 32 + nt * 8 + g) * P2 + kb;
            bf2[nt][0] = *reinterpret_cast<uint32_t*>(p);
            bf2[nt][1] = *reinterpret_cast<uint32_t*>(p + 16);
        }
        #pragma unroll
        for (int mt = 0; mt < 4; mt++)
            #pragma unroll
            for (int nt = 0; nt < 4; nt++)
                mma_f16(acc[mt][nt], af[mt], bf2[nt]);
    }
    __syncthreads();

    // Stage transposed fp16 output Os[f][g] for coalesced YsT_h writes
    char* Os = Xs;
    #pragma unroll
    for (int mt = 0; mt < 4; mt++) {
        const int gl0 = wm * 64 + mt * 16 + g;
        const int gg0 = m0g + gl0;
        const float d0 = g_dinv[gg0];
        const float d1 = g_dinv[gg0 + 8];
        #pragma unroll
        for (int nt = 0; nt < 4; nt++) {
            const int f = wn * 32 + nt * 8 + tig * 2;
            float c0 = acc[mt][nt][0] * d0, c1 = acc[mt][nt][1] * d0;
            float c2 = acc[mt][nt][2] * d1, c3 = acc[mt][nt][3] * d1;
            *reinterpret_cast<__half*>(Os + f * P2 + gl0 * 2)             = __float2half_rn(c0);
            *reinterpret_cast<__half*>(Os + (f + 1) * P2 + gl0 * 2)       = __float2half_rn(c1);
            *reinterpret_cast<__half*>(Os + f * P2 + (gl0 + 8) * 2)       = __float2half_rn(c2);
            *reinterpret_cast<__half*>(Os + (f + 1) * P2 + (gl0 + 8) * 2) = __float2half_rn(c3);
        }
    }
    __syncthreads();
    {
        const int f = tid >> 1, half = tid & 1;
        char* src = Os + f * P2 + half * 128;
        __half* dst = g_YsT_h + (size_t)f * GTOT + m0g + half * 64;
        #pragma unroll
        for (int j = 0; j < 8; j++)
            *reinterpret_cast<uint4*>(dst + j * 8) = *reinterpret_cast<uint4*>(src + j * 16);
    }
}

// ---------------------------------------------------------------------------
// Kernel 3: out += d_n * ( (A+I)[b,n,kh*512:+512] @ Ysd[b][kh*512:+512,:] )
//   R12 config (measured 28.8 us): 2-way K-split, grid (8,16,2) = 256 CTAs,
//   2 CTAs/SM.  CTA 128x128, K-chunk 64, 3-stage cp.async, ldmatrix + mma.
//   Partials combined via atomicAdd onto zeroed output (deterministic).
// ---------------------------------------------------------------------------
#define PA3 144                     // 64 fp16 = 128B + 16B pad
#define TA3 (128 * PA3)             // 18432
#define STG3 (2 * TA3)              // 36864 (A + B per stage)
#define NSTAGE 3
#define SMEM3 (NSTAGE * STG3)       // 110592 (x2 CTAs = 216 KB/SM)
#define KSPLIT 2
#define NCHUNK (NN / KSPLIT / 64)   // 8

__global__ void __launch_bounds__(256, 2) gemm_mma(float* __restrict__ out) {
    extern __shared__ char sm[];
    const uint32_t sb = smem_to_u32(sm);

    const int tid = threadIdx.x;
    const int wid = tid >> 5, lane = tid & 31;
    const int g = lane >> 2, tig = lane & 3;
    const int wm = wid & 1, wn = wid >> 1;
    const int b = blockIdx.y;
    const int rowStart = blockIdx.x * 128;
    const int k0 = blockIdx.z * (NN / KSPLIT);   // 0 or 512

    // cp.async mapping: row = tid>>1, half = tid&1 (32 of 64 k-values, 64B)
    const int cr = tid >> 1;
    const int ch = tid & 1;
    const __half* Ap = g_Ah + ((size_t)b * NN + rowStart + cr) * NN + k0 + ch * 32;
    const __half* Bp = g_YsT_h + (size_t)cr * GTOT + (size_t)b * NN + k0 + ch * 32;
    const uint32_t dA0 = sb + cr * PA3 + ch * 64;
    const uint32_t dB0 = dA0 + TA3;

    auto issue = [&](int kc) {
        const uint32_t s = (kc % NSTAGE) * STG3;
        const __half* pa = Ap + kc * 64;
        const __half* pb = Bp + kc * 64;
        #pragma unroll
        for (int j = 0; j < 4; j++) CP_ASYNC_16(dA0 + s + j * 16, pa + j * 8);
        #pragma unroll
        for (int j = 0; j < 4; j++) CP_ASYNC_16(dB0 + s + j * 16, pb + j * 8);
        CP_ASYNC_COMMIT();
    };

    // ldmatrix lane addressing
    const int t = lane >> 3, r8 = lane & 7;
    const uint32_t aOff = (uint32_t)(wm * 64 + (t & 1) * 8 + r8) * PA3 + ((t >> 1) * 8) * 2;
    const uint32_t bOff = TA3 + (uint32_t)(wn * 32 + (t >> 1) * 8 + r8) * PA3 + ((t & 1) * 8) * 2;

    float acc[4][4][4];
    #pragma unroll
    for (int i = 0; i < 4; i++)
        #pragma unroll
        for (int j = 0; j < 4; j++)
            #pragma unroll
            for (int k = 0; k < 4; k++) acc[i][j][k] = 0.f;

    issue(0);
    issue(1);

    for (int kc = 0; kc < NCHUNK; kc++) {
        if (kc < NCHUNK - 1) { CP_ASYNC_WAIT1(); } else { CP_ASYNC_WAIT0(); }
        __syncthreads();
        if (kc + 2 < NCHUNK) issue(kc + 2);

        const uint32_t st = sb + (kc % NSTAGE) * STG3;

        #pragma unroll
        for (int ks = 0; ks < 4; ks++) {
            uint32_t af[4][4], bf2[4][2];
            #pragma unroll
            for (int mt = 0; mt < 4; mt++)
                LDSM_X4(af[mt][0], af[mt][1], af[mt][2], af[mt][3],
                        st + aOff + (uint32_t)mt * 16 * PA3 + ks * 32);
            #pragma unroll
            for (int np = 0; np < 2; np++)
                LDSM_X4(bf2[np * 2][0], bf2[np * 2][1], bf2[np * 2 + 1][0], bf2[np * 2 + 1][1],
                        st + bOff + (uint32_t)np * 16 * PA3 + ks * 32);
            #pragma unroll
            for (int mt = 0; mt < 4; mt++)
                #pragma unroll
                for (int nt = 0; nt < 4; nt++)
                    mma_f16(acc[mt][nt], af[mt], bf2[nt]);
        }
    }

    // Epilogue: out += d_n * acc   (K-split partial, atomic accumulate)
    #pragma unroll
    for (int mt = 0; mt < 4; mt++) {
        const int gr0 = b * NN + rowStart + wm * 64 + mt * 16 + g;
        const float d0 = g_dinv[gr0];
        const float d1 = g_dinv[gr0 + 8];
        float* o0 = out + (size_t)gr0 * FF + wn * 32 + tig * 2;
        float* o1 = o0 + (size_t)8 * FF;
        #pragma unroll
        for (int nt = 0; nt < 4; nt++) {
            atomicAdd(o0 + nt * 8,     d0 * acc[mt][nt][0]);
            atomicAdd(o0 + nt * 8 + 1, d0 * acc[mt][nt][1]);
            atomicAdd(o1 + nt * 8,     d1 * acc[mt][nt][2]);
            atomicAdd(o1 + nt * 8 + 1, d1 * acc[mt][nt][3]);
        }
    }
}

// ---------------------------------------------------------------------------
// kernel_launch
// ---------------------------------------------------------------------------
extern "C" void kernel_launch(void* const* d_in, const int* in_sizes, int n_in,
                              void* d_out, int out_size) {
    const float* X = (const float*)d_in[0];   // [16,1024,128]
    const float* A = (const float*)d_in[1];   // [16,1024,1024]
    const float* W = (const float*)d_in[2];   // [128,128]
    float* out = (float*)d_out;               // [16,1024,128]

    cudaFuncSetAttribute(gemm_xw_t, cudaFuncAttributeMaxDynamicSharedMemorySize, SMEM2);
    cudaFuncSetAttribute(gemm_mma, cudaFuncAttributeMaxDynamicSharedMemorySize, SMEM3);

    // 0) zero the output (mma atomically accumulates K-split partials)
    zero_out<<<(GTOT * FF) / (256 * 4), 256>>>(out);

    // 1) dinv = rsqrt(rowsum(A)+1)  +  Ah = fp16(A) (fused)
    deg_kernel<<<GTOT / 16, 256>>>(A);

    // 2) YsT_h = fp16(d_m * (X @ W)) transposed  +  Ah diagonal patch (+I)
    gemm_xw_t<<<GTOT / 128, 256, SMEM2>>>(X, W, A);

    // 3) out += d_n * ((A+I) @ Ysd)  via 2-way K-split ldmatrix + fp16 mma.sync
    {
        dim3 grid(NN / 128, BATCH, KSPLIT);
        gemm_mma<<<grid, 256, SMEM3>>>(out);
    }
}

// round 15
// speedup vs baseline: 1.4923x; 1.0293x over previous
#include <cuda_runtime.h>
#include <cuda_fp16.h>
#include <cstdint>

// Problem constants
#define BATCH 16
#define NN    1024
#define FF    128
#define GTOT  (BATCH * NN)     // 16384

// ---------------------------------------------------------------------------
// Device-global scratch (no allocations allowed)
// ---------------------------------------------------------------------------
__device__ float  g_dinv[GTOT];             // 64 KB
__device__ __half g_Ah[(size_t)GTOT * NN];  // 32 MB  (A, diag patched to A+1) fp16
__device__ __half g_YsT_h[FF * GTOT];       // 4 MB   [f][g] fp16, d_m-scaled

// ---------------------------------------------------------------------------
// Helpers
// ---------------------------------------------------------------------------
__device__ __forceinline__ uint32_t smem_to_u32(const void* p) {
    uint32_t a;
    asm("{ .reg .u64 t; cvta.to.shared.u64 t, %1; cvt.u32.u64 %0, t; }" : "=r"(a) : "l"(p));
    return a;
}
#define CP_ASYNC_16(dst_u32, src) \
    asm volatile("cp.async.cg.shared.global [%0], [%1], 16;" \
                 :: "r"(dst_u32), "l"(src) : "memory")
#define CP_ASYNC_COMMIT()  asm volatile("cp.async.commit_group;" ::: "memory")
#define CP_ASYNC_WAIT1()   asm volatile("cp.async.wait_group 1;" ::: "memory")
#define CP_ASYNC_WAIT0()   asm volatile("cp.async.wait_group 0;" ::: "memory")

#define LDSM_X4(r0, r1, r2, r3, addr) \
    asm volatile("ldmatrix.sync.aligned.m8n8.x4.shared.b16 {%0,%1,%2,%3}, [%4];" \
                 : "=r"(r0), "=r"(r1), "=r"(r2), "=r"(r3) : "r"(addr))

__device__ __forceinline__ void mma_f16(float* c, const uint32_t* a, const uint32_t* b) {
    asm volatile(
        "mma.sync.aligned.m16n8k16.row.col.f32.f16.f16.f32 "
        "{%0,%1,%2,%3}, {%4,%5,%6,%7}, {%8,%9}, {%0,%1,%2,%3};\n"
        : "+f"(c[0]), "+f"(c[1]), "+f"(c[2]), "+f"(c[3])
        : "r"(a[0]), "r"(a[1]), "r"(a[2]), "r"(a[3]), "r"(b[0]), "r"(b[1]));
}
__device__ __forceinline__ uint32_t pack_h2(float x, float y) {
    __half2 h = __floats2half2_rn(x, y);
    return reinterpret_cast<uint32_t&>(h);
}

// ---------------------------------------------------------------------------
// Kernel 1: dinv[row] = rsqrt(rowsum(A)+1)  AND  g_Ah = fp16(A)
//   AND zero the output (fused — deletes the zero_out launch).
// ---------------------------------------------------------------------------
__global__ void __launch_bounds__(256) deg_kernel(const float* __restrict__ A,
                                                  float* __restrict__ out) {
    // Zero 8 output floats per thread (grid 1024 x 256 x 8 = 2M = GTOT*FF)
    {
        const size_t i = ((size_t)blockIdx.x * 256 + threadIdx.x) * 8;
        *reinterpret_cast<float4*>(out + i)     = make_float4(0.f, 0.f, 0.f, 0.f);
        *reinterpret_cast<float4*>(out + i + 4) = make_float4(0.f, 0.f, 0.f, 0.f);
    }

    const int wid = threadIdx.x >> 5, lid = threadIdx.x & 31;
    const int row0 = blockIdx.x * 16 + wid * 2;
    const float4* r0 = reinterpret_cast<const float4*>(A + (size_t)row0 * NN);
    const float4* r1 = reinterpret_cast<const float4*>(A + (size_t)(row0 + 1) * NN);
    __half* h0 = g_Ah + (size_t)row0 * NN;
    __half* h1 = h0 + NN;
    float s0 = 0.f, s1 = 0.f;
    #pragma unroll
    for (int i = 0; i < 8; i++) {
        float4 a = r0[lid + i * 32];
        float4 b = r1[lid + i * 32];
        s0 += (a.x + a.y) + (a.z + a.w);
        s1 += (b.x + b.y) + (b.z + b.w);
        uint2 pa = make_uint2(pack_h2(a.x, a.y), pack_h2(a.z, a.w));
        uint2 pb = make_uint2(pack_h2(b.x, b.y), pack_h2(b.z, b.w));
        *reinterpret_cast<uint2*>(h0 + (lid + i * 32) * 4) = pa;
        *reinterpret_cast<uint2*>(h1 + (lid + i * 32) * 4) = pb;
    }
    #pragma unroll
    for (int o = 16; o; o >>= 1) {
        s0 += __shfl_xor_sync(0xFFFFFFFFu, s0, o);
        s1 += __shfl_xor_sync(0xFFFFFFFFu, s1, o);
    }
    if (lid == 0) {
        g_dinv[row0]     = rsqrtf(s0 + 1.0f);
        g_dinv[row0 + 1] = rsqrtf(s1 + 1.0f);
    }
}

// ---------------------------------------------------------------------------
// Kernel 2: YsT_h[f][g] = fp16( d_g * (X @ W)[g][f] )  computed TRANSPOSED:
//   D[f][g] = (W^T @ X^T)[f][g].  M-dim = f, N-dim = g -> the fragment holds
//   g-adjacent pairs, so YsT is written directly as half2 stores (no staging).
//   PLUS diagonal patch: g_Ah[g][g%N] = fp16(A[g][g%N] + 1).
//   grid = 128 (one CTA per 128-g block), block 256 = 8 warps (2f x 4g).
// ---------------------------------------------------------------------------
#define P2 272                     // 128 fp16 = 256B + 16B pad
#define T2 (128 * P2)              // 34816 per tile
#define SMEM2 (2 * T2)             // 69632  (Wt + Xh)

__global__ void __launch_bounds__(256) gemm_xw_t(const float* __restrict__ X,
                                                 const float* __restrict__ W,
                                                 const float* __restrict__ A) {
    extern __shared__ char sm2[];
    char* Wt = sm2;                // Wt[f][k] = W[k][f]
    char* Xh = sm2 + T2;           // Xh[g][k] = fp16(X[g0+g][k])
    const uint32_t sb = smem_to_u32(sm2);

    const int tid = threadIdx.x;
    const int lane = tid & 31;
    const int wid = tid >> 5;
    const int wm = wid & 1, wn = wid >> 1;     // wm: f-half, wn: g-quarter
    const int g0 = blockIdx.x * 128;

    // Diagonal patch (A+I folded into Ah) for this block's 128 rows
    if (tid < 128) {
        const int gr = g0 + tid;
        const int dc = gr & (NN - 1);
        const size_t idx = (size_t)gr * NN + dc;
        g_Ah[idx] = __float2half_rn(A[idx] + 1.0f);
    }

    // Stage W transposed: Wt[f][k] = W[k][f]
    for (int idx = tid; idx < 128 * 128; idx += 256) {
        int k = idx >> 7, f = idx & 127;
        *reinterpret_cast<__half*>(Wt + f * P2 + k * 2) = __float2half_rn(W[idx]);
    }
    // Stage X rows as fp16: Xh[g][k]
    {
        const int r = tid >> 1, half = tid & 1;
        const float* xp = X + (size_t)(g0 + r) * FF + half * 64;
        char* dst = Xh + r * P2 + half * 128;
        #pragma unroll
        for (int j = 0; j < 8; j++) {
            float4 v0 = *reinterpret_cast<const float4*>(xp + j * 8);
            float4 v1 = *reinterpret_cast<const float4*>(xp + j * 8 + 4);
            uint4 o;
            o.x = pack_h2(v0.x, v0.y); o.y = pack_h2(v0.z, v0.w);
            o.z = pack_h2(v1.x, v1.y); o.w = pack_h2(v1.z, v1.w);
            *reinterpret_cast<uint4*>(dst + j * 16) = o;
        }
    }
    __syncthreads();

    // ldmatrix lane addressing (same pattern as kernel 3)
    const int t = lane >> 3, r8 = lane & 7;
    const uint32_t aOff = (uint32_t)(wm * 64 + (t & 1) * 8 + r8) * P2 + ((t >> 1) * 8) * 2;          // Wt
    const uint32_t bOff = (uint32_t)T2 + (uint32_t)(wn * 32 + (t >> 1) * 8 + r8) * P2 + ((t & 1) * 8) * 2; // Xh

    float acc[4][4][4];
    #pragma unroll
    for (int i = 0; i < 4; i++)
        #pragma unroll
        for (int j = 0; j < 4; j++)
            #pragma unroll
            for (int k = 0; k < 4; k++) acc[i][j][k] = 0.f;

    #pragma unroll
    for (int ks = 0; ks < 8; ks++) {
        uint32_t af[4][4], bf2[4][2];
        #pragma unroll
        for (int mt = 0; mt < 4; mt++)
            LDSM_X4(af[mt][0], af[mt][1], af[mt][2], af[mt][3],
                    sb + aOff + (uint32_t)mt * 16 * P2 + ks * 32);
        #pragma unroll
        for (int np = 0; np < 2; np++)
            LDSM_X4(bf2[np * 2][0], bf2[np * 2][1], bf2[np * 2 + 1][0], bf2[np * 2 + 1][1],
                    sb + bOff + (uint32_t)np * 16 * P2 + ks * 32);
        #pragma unroll
        for (int mt = 0; mt < 4; mt++)
            #pragma unroll
            for (int nt = 0; nt < 4; nt++)
                mma_f16(acc[mt][nt], af[mt], bf2[nt]);
    }

    // Epilogue: scale by d_g and store half2 pairs straight to g_YsT_h[f][g]
    const int g8 = lane >> 2, tig = lane & 3;
    #pragma unroll
    for (int mt = 0; mt < 4; mt++) {
        const int f0 = wm * 64 + mt * 16 + g8;        // fragment rows f0, f0+8
        #pragma unroll
        for (int nt = 0; nt < 4; nt++) {
            const int gc = g0 + wn * 32 + nt * 8 + tig * 2;
            const float2 d = *reinterpret_cast<const float2*>(&g_dinv[gc]);
            uint32_t p0 = pack_h2(acc[mt][nt][0] * d.x, acc[mt][nt][1] * d.y);
            uint32_t p1 = pack_h2(acc[mt][nt][2] * d.x, acc[mt][nt][3] * d.y);
            *reinterpret_cast<uint32_t*>(&g_YsT_h[(size_t)f0 * GTOT + gc])       = p0;
            *reinterpret_cast<uint32_t*>(&g_YsT_h[(size_t)(f0 + 8) * GTOT + gc]) = p1;
        }
    }
}

// ---------------------------------------------------------------------------
// Kernel 3: out += d_n * ( (A+I)[b,n,kh*512:+512] @ Ysd[b][kh*512:+512,:] )
//   R12/R14 config (measured 28.6-28.8 us): 2-way K-split, grid (8,16,2),
//   2 CTAs/SM.  CTA 128x128, K-chunk 64, 3-stage cp.async, ldmatrix + mma.
//   Partials combined via atomicAdd onto zeroed output (deterministic).
// ---------------------------------------------------------------------------
#define PA3 144                     // 64 fp16 = 128B + 16B pad
#define TA3 (128 * PA3)             // 18432
#define STG3 (2 * TA3)              // 36864 (A + B per stage)
#define NSTAGE 3
#define SMEM3 (NSTAGE * STG3)       // 110592 (x2 CTAs = 216 KB/SM)
#define KSPLIT 2
#define NCHUNK (NN / KSPLIT / 64)   // 8

__global__ void __launch_bounds__(256, 2) gemm_mma(float* __restrict__ out) {
    extern __shared__ char sm[];
    const uint32_t sb = smem_to_u32(sm);

    const int tid = threadIdx.x;
    const int wid = tid >> 5, lane = tid & 31;
    const int g = lane >> 2, tig = lane & 3;
    const int wm = wid & 1, wn = wid >> 1;
    const int b = blockIdx.y;
    const int rowStart = blockIdx.x * 128;
    const int k0 = blockIdx.z * (NN / KSPLIT);   // 0 or 512

    // cp.async mapping: row = tid>>1, half = tid&1 (32 of 64 k-values, 64B)
    const int cr = tid >> 1;
    const int ch = tid & 1;
    const __half* Ap = g_Ah + ((size_t)b * NN + rowStart + cr) * NN + k0 + ch * 32;
    const __half* Bp = g_YsT_h + (size_t)cr * GTOT + (size_t)b * NN + k0 + ch * 32;
    const uint32_t dA0 = sb + cr * PA3 + ch * 64;
    const uint32_t dB0 = dA0 + TA3;

    auto issue = [&](int kc) {
        const uint32_t s = (kc % NSTAGE) * STG3;
        const __half* pa = Ap + kc * 64;
        const __half* pb = Bp + kc * 64;
        #pragma unroll
        for (int j = 0; j < 4; j++) CP_ASYNC_16(dA0 + s + j * 16, pa + j * 8);
        #pragma unroll
        for (int j = 0; j < 4; j++) CP_ASYNC_16(dB0 + s + j * 16, pb + j * 8);
        CP_ASYNC_COMMIT();
    };

    // ldmatrix lane addressing
    const int t = lane >> 3, r8 = lane & 7;
    const uint32_t aOff = (uint32_t)(wm * 64 + (t & 1) * 8 + r8) * PA3 + ((t >> 1) * 8) * 2;
    const uint32_t bOff = TA3 + (uint32_t)(wn * 32 + (t >> 1) * 8 + r8) * PA3 + ((t & 1) * 8) * 2;

    float acc[4][4][4];
    #pragma unroll
    for (int i = 0; i < 4; i++)
        #pragma unroll
        for (int j = 0; j < 4; j++)
            #pragma unroll
            for (int k = 0; k < 4; k++) acc[i][j][k] = 0.f;

    issue(0);
    issue(1);

    for (int kc = 0; kc < NCHUNK; kc++) {
        if (kc < NCHUNK - 1) { CP_ASYNC_WAIT1(); } else { CP_ASYNC_WAIT0(); }
        __syncthreads();
        if (kc + 2 < NCHUNK) issue(kc + 2);

        const uint32_t st = sb + (kc % NSTAGE) * STG3;

        #pragma unroll
        for (int ks = 0; ks < 4; ks++) {
            uint32_t af[4][4], bf2[4][2];
            #pragma unroll
            for (int mt = 0; mt < 4; mt++)
                LDSM_X4(af[mt][0], af[mt][1], af[mt][2], af[mt][3],
                        st + aOff + (uint32_t)mt * 16 * PA3 + ks * 32);
            #pragma unroll
            for (int np = 0; np < 2; np++)
                LDSM_X4(bf2[np * 2][0], bf2[np * 2][1], bf2[np * 2 + 1][0], bf2[np * 2 + 1][1],
                        st + bOff + (uint32_t)np * 16 * PA3 + ks * 32);
            #pragma unroll
            for (int mt = 0; mt < 4; mt++)
                #pragma unroll
                for (int nt = 0; nt < 4; nt++)
                    mma_f16(acc[mt][nt], af[mt], bf2[nt]);
        }
    }

    // Epilogue: out += d_n * acc   (K-split partial, atomic accumulate)
    #pragma unroll
    for (int mt = 0; mt < 4; mt++) {
        const int gr0 = b * NN + rowStart + wm * 64 + mt * 16 + g;
        const float d0 = g_dinv[gr0];
        const float d1 = g_dinv[gr0 + 8];
        float* o0 = out + (size_t)gr0 * FF + wn * 32 + tig * 2;
        float* o1 = o0 + (size_t)8 * FF;
        #pragma unroll
        for (int nt = 0; nt < 4; nt++) {
            atomicAdd(o0 + nt * 8,     d0 * acc[mt][nt][0]);
            atomicAdd(o0 + nt * 8 + 1, d0 * acc[mt][nt][1]);
            atomicAdd(o1 + nt * 8,     d1 * acc[mt][nt][2]);
            atomicAdd(o1 + nt * 8 + 1, d1 * acc[mt][nt][3]);
        }
    }
}

// ---------------------------------------------------------------------------
// kernel_launch
// ---------------------------------------------------------------------------
extern "C" void kernel_launch(void* const* d_in, const int* in_sizes, int n_in,
                              void* d_out, int out_size) {
    const float* X = (const float*)d_in[0];   // [16,1024,128]
    const float* A = (const float*)d_in[1];   // [16,1024,1024]
    const float* W = (const float*)d_in[2];   // [128,128]
    float* out = (float*)d_out;               // [16,1024,128]

    cudaFuncSetAttribute(gemm_xw_t, cudaFuncAttributeMaxDynamicSharedMemorySize, SMEM2);
    cudaFuncSetAttribute(gemm_mma, cudaFuncAttributeMaxDynamicSharedMemorySize, SMEM3);

    // 1) dinv = rsqrt(rowsum(A)+1)  +  Ah = fp16(A)  +  zero out (fused)
    deg_kernel<<<GTOT / 16, 256>>>(A, out);

    // 2) YsT_h = fp16(d_g * (X @ W)^T) computed transposed, direct stores
    //    + Ah diagonal patch (+I)
    gemm_xw_t<<<GTOT / 128, 256, SMEM2>>>(X, W, A);

    // 3) out += d_n * ((A+I) @ Ysd)  via 2-way K-split ldmatrix + fp16 mma.sync
    {
        dim3 grid(NN / 128, BATCH, KSPLIT);
        gemm_mma<<<grid, 256, SMEM3>>>(out);
    }
}

// round 16
// speedup vs baseline: 1.5441x; 1.0347x over previous
#include <cuda_runtime.h>
#include <cuda_fp16.h>
#include <cstdint>

// Problem constants
#define BATCH 16
#define NN    1024
#define FF    128
#define GTOT  (BATCH * NN)     // 16384

// ---------------------------------------------------------------------------
// Device-global scratch (no allocations allowed)
// ---------------------------------------------------------------------------
__device__ float  g_dinv[GTOT];             // 64 KB
__device__ __half g_Ah[(size_t)GTOT * NN];  // 32 MB  (A, diag patched to A+1) fp16
__device__ __half g_YsT_h[FF * GTOT];       // 4 MB   [f][g] fp16, d_m-scaled

// ---------------------------------------------------------------------------
// Helpers
// ---------------------------------------------------------------------------
__device__ __forceinline__ uint32_t smem_to_u32(const void* p) {
    uint32_t a;
    asm("{ .reg .u64 t; cvta.to.shared.u64 t, %1; cvt.u32.u64 %0, t; }" : "=r"(a) : "l"(p));
    return a;
}
#define CP_ASYNC_16(dst_u32, src) \
    asm volatile("cp.async.cg.shared.global [%0], [%1], 16;" \
                 :: "r"(dst_u32), "l"(src) : "memory")
#define CP_ASYNC_COMMIT()  asm volatile("cp.async.commit_group;" ::: "memory")
#define CP_ASYNC_WAIT1()   asm volatile("cp.async.wait_group 1;" ::: "memory")
#define CP_ASYNC_WAIT0()   asm volatile("cp.async.wait_group 0;" ::: "memory")

#define LDSM_X4(r0, r1, r2, r3, addr) \
    asm volatile("ldmatrix.sync.aligned.m8n8.x4.shared.b16 {%0,%1,%2,%3}, [%4];" \
                 : "=r"(r0), "=r"(r1), "=r"(r2), "=r"(r3) : "r"(addr))

#define RED_ADD_V2(ptr, x, y) \
    asm volatile("red.global.add.v2.f32 [%0], {%1, %2};" \
                 :: "l"(ptr), "f"(x), "f"(y) : "memory")

__device__ __forceinline__ void mma_f16(float* c, const uint32_t* a, const uint32_t* b) {
    asm volatile(
        "mma.sync.aligned.m16n8k16.row.col.f32.f16.f16.f32 "
        "{%0,%1,%2,%3}, {%4,%5,%6,%7}, {%8,%9}, {%0,%1,%2,%3};\n"
        : "+f"(c[0]), "+f"(c[1]), "+f"(c[2]), "+f"(c[3])
        : "r"(a[0]), "r"(a[1]), "r"(a[2]), "r"(a[3]), "r"(b[0]), "r"(b[1]));
}
__device__ __forceinline__ uint32_t pack_h2(float x, float y) {
    __half2 h = __floats2half2_rn(x, y);
    return reinterpret_cast<uint32_t&>(h);
}

// ---------------------------------------------------------------------------
// Kernel 1: dinv[row] = rsqrt(rowsum(A)+1)  AND  g_Ah = fp16(A)
//   AND zero the output (fused).  (R15 version, measured 16.1 us)
// ---------------------------------------------------------------------------
__global__ void __launch_bounds__(256) deg_kernel(const float* __restrict__ A,
                                                  float* __restrict__ out) {
    {
        const size_t i = ((size_t)blockIdx.x * 256 + threadIdx.x) * 8;
        *reinterpret_cast<float4*>(out + i)     = make_float4(0.f, 0.f, 0.f, 0.f);
        *reinterpret_cast<float4*>(out + i + 4) = make_float4(0.f, 0.f, 0.f, 0.f);
    }

    const int wid = threadIdx.x >> 5, lid = threadIdx.x & 31;
    const int row0 = blockIdx.x * 16 + wid * 2;
    const float4* r0 = reinterpret_cast<const float4*>(A + (size_t)row0 * NN);
    const float4* r1 = reinterpret_cast<const float4*>(A + (size_t)(row0 + 1) * NN);
    __half* h0 = g_Ah + (size_t)row0 * NN;
    __half* h1 = h0 + NN;
    float s0 = 0.f, s1 = 0.f;
    #pragma unroll
    for (int i = 0; i < 8; i++) {
        float4 a = r0[lid + i * 32];
        float4 b = r1[lid + i * 32];
        s0 += (a.x + a.y) + (a.z + a.w);
        s1 += (b.x + b.y) + (b.z + b.w);
        uint2 pa = make_uint2(pack_h2(a.x, a.y), pack_h2(a.z, a.w));
        uint2 pb = make_uint2(pack_h2(b.x, b.y), pack_h2(b.z, b.w));
        *reinterpret_cast<uint2*>(h0 + (lid + i * 32) * 4) = pa;
        *reinterpret_cast<uint2*>(h1 + (lid + i * 32) * 4) = pb;
    }
    #pragma unroll
    for (int o = 16; o; o >>= 1) {
        s0 += __shfl_xor_sync(0xFFFFFFFFu, s0, o);
        s1 += __shfl_xor_sync(0xFFFFFFFFu, s1, o);
    }
    if (lid == 0) {
        g_dinv[row0]     = rsqrtf(s0 + 1.0f);
        g_dinv[row0 + 1] = rsqrtf(s1 + 1.0f);
    }
}

// ---------------------------------------------------------------------------
// Kernel 2: YsT_h[f][g] = fp16( d_g * (X @ W)[g][f] ), computed transposed
//   as D[f][g] = (W^T @ X^T), tiled 64(f) x 128(g) per CTA.
//   grid = (128 g-tiles, 2 f-tiles) = 256 CTAs; block 256 = 8 warps (1f x 8g),
//   warp tile 64f x 16g.  Fragment g-pairs -> direct half2 stores.
//   PLUS diagonal patch (f-tile 0 only): g_Ah[g][g%N] = fp16(A[..] + 1).
// ---------------------------------------------------------------------------
#define P2 272                     // 128 fp16 = 256B + 16B pad
#define WT_SZ (64 * P2)            // 17408
#define XH_SZ (128 * P2)           // 34816
#define SMEM2 (WT_SZ + XH_SZ)      // 52224

__global__ void __launch_bounds__(256) gemm_xw_t(const float* __restrict__ X,
                                                 const float* __restrict__ W,
                                                 const float* __restrict__ A) {
    extern __shared__ char sm2[];
    char* Wt = sm2;                // Wt[fl][k] = W[k][fbase + fl], fl in [0,64)
    char* Xh = sm2 + WT_SZ;        // Xh[g][k]  = fp16(X[g0+g][k])
    const uint32_t sb = smem_to_u32(sm2);

    const int tid = threadIdx.x;
    const int lane = tid & 31;
    const int wn = tid >> 5;                   // warp = g-sixteenth (0..7)
    const int g0 = blockIdx.x * 128;
    const int fbase = blockIdx.y * 64;

    // Diagonal patch (A+I into Ah) — f-tile 0 CTAs only, once per g row
    if (blockIdx.y == 0 && tid < 128) {
        const int gr = g0 + tid;
        const int dc = gr & (NN - 1);
        const size_t idx = (size_t)gr * NN + dc;
        g_Ah[idx] = __float2half_rn(A[idx] + 1.0f);
    }

    // Stage Wt (64 f-rows): Wt[fl][k] = W[k][fbase+fl]
    for (int idx = tid; idx < 64 * 128; idx += 256) {
        const int k = idx >> 6, fl = idx & 63;
        *reinterpret_cast<__half*>(Wt + fl * P2 + k * 2) =
            __float2half_rn(W[k * FF + fbase + fl]);
    }
    // Stage Xh (128 g-rows, fp16)
    {
        const int r = tid >> 1, half = tid & 1;
        const float* xp = X + (size_t)(g0 + r) * FF + half * 64;
        char* dst = Xh + r * P2 + half * 128;
        #pragma unroll
        for (int j = 0; j < 8; j++) {
            float4 v0 = *reinterpret_cast<const float4*>(xp + j * 8);
            float4 v1 = *reinterpret_cast<const float4*>(xp + j * 8 + 4);
            uint4 o;
            o.x = pack_h2(v0.x, v0.y); o.y = pack_h2(v0.z, v0.w);
            o.z = pack_h2(v1.x, v1.y); o.w = pack_h2(v1.z, v1.w);
            *reinterpret_cast<uint4*>(dst + j * 16) = o;
        }
    }
    __syncthreads();

    // ldmatrix lane addressing
    const int t = lane >> 3, r8 = lane & 7;
    const uint32_t aOff = (uint32_t)((t & 1) * 8 + r8) * P2 + ((t >> 1) * 8) * 2;  // + mt*16*P2
    const uint32_t bOff = (uint32_t)WT_SZ +
        (uint32_t)(wn * 16 + (t >> 1) * 8 + r8) * P2 + ((t & 1) * 8) * 2;

    float acc[4][2][4];
    #pragma unroll
    for (int i = 0; i < 4; i++)
        #pragma unroll
        for (int j = 0; j < 2; j++)
            #pragma unroll
            for (int k = 0; k < 4; k++) acc[i][j][k] = 0.f;

    #pragma unroll
    for (int ks = 0; ks < 8; ks++) {
        uint32_t af[4][4], bf2[2][2];
        #pragma unroll
        for (int mt = 0; mt < 4; mt++)
            LDSM_X4(af[mt][0], af[mt][1], af[mt][2], af[mt][3],
                    sb + aOff + (uint32_t)mt * 16 * P2 + ks * 32);
        LDSM_X4(bf2[0][0], bf2[0][1], bf2[1][0], bf2[1][1],
                sb + bOff + ks * 32);
        #pragma unroll
        for (int mt = 0; mt < 4; mt++)
            #pragma unroll
            for (int nt = 0; nt < 2; nt++)
                mma_f16(acc[mt][nt], af[mt], bf2[nt]);
    }

    // Epilogue: scale by d_g, store half2 pairs straight to g_YsT_h[f][g]
    const int g8 = lane >> 2, tig = lane & 3;
    #pragma unroll
    for (int mt = 0; mt < 4; mt++) {
        const int f0 = fbase + mt * 16 + g8;          // fragment rows f0, f0+8
        #pragma unroll
        for (int nt = 0; nt < 2; nt++) {
            const int gc = g0 + wn * 16 + nt * 8 + tig * 2;
            const float2 d = *reinterpret_cast<const float2*>(&g_dinv[gc]);
            uint32_t p0 = pack_h2(acc[mt][nt][0] * d.x, acc[mt][nt][1] * d.y);
            uint32_t p1 = pack_h2(acc[mt][nt][2] * d.x, acc[mt][nt][3] * d.y);
            *reinterpret_cast<uint32_t*>(&g_YsT_h[(size_t)f0 * GTOT + gc])       = p0;
            *reinterpret_cast<uint32_t*>(&g_YsT_h[(size_t)(f0 + 8) * GTOT + gc]) = p1;
        }
    }
}

// ---------------------------------------------------------------------------
// Kernel 3: out += d_n * ( (A+I)[b,n,kh*512:+512] @ Ysd[b][kh*512:+512,:] )
//   R12/R14 mainloop (measured 28.6-28.8 us) — UNCHANGED.  Epilogue upgraded
//   to red.global.add.v2.f32 (fire-and-forget vector reduction).
// ---------------------------------------------------------------------------
#define PA3 144                     // 64 fp16 = 128B + 16B pad
#define TA3 (128 * PA3)             // 18432
#define STG3 (2 * TA3)              // 36864 (A + B per stage)
#define NSTAGE 3
#define SMEM3 (NSTAGE * STG3)       // 110592 (x2 CTAs = 216 KB/SM)
#define KSPLIT 2
#define NCHUNK (NN / KSPLIT / 64)   // 8

__global__ void __launch_bounds__(256, 2) gemm_mma(float* __restrict__ out) {
    extern __shared__ char sm[];
    const uint32_t sb = smem_to_u32(sm);

    const int tid = threadIdx.x;
    const int wid = tid >> 5, lane = tid & 31;
    const int g = lane >> 2, tig = lane & 3;
    const int wm = wid & 1, wn = wid >> 1;
    const int b = blockIdx.y;
    const int rowStart = blockIdx.x * 128;
    const int k0 = blockIdx.z * (NN / KSPLIT);   // 0 or 512

    // cp.async mapping: row = tid>>1, half = tid&1 (32 of 64 k-values, 64B)
    const int cr = tid >> 1;
    const int ch = tid & 1;
    const __half* Ap = g_Ah + ((size_t)b * NN + rowStart + cr) * NN + k0 + ch * 32;
    const __half* Bp = g_YsT_h + (size_t)cr * GTOT + (size_t)b * NN + k0 + ch * 32;
    const uint32_t dA0 = sb + cr * PA3 + ch * 64;
    const uint32_t dB0 = dA0 + TA3;

    auto issue = [&](int kc) {
        const uint32_t s = (kc % NSTAGE) * STG3;
        const __half* pa = Ap + kc * 64;
        const __half* pb = Bp + kc * 64;
        #pragma unroll
        for (int j = 0; j < 4; j++) CP_ASYNC_16(dA0 + s + j * 16, pa + j * 8);
        #pragma unroll
        for (int j = 0; j < 4; j++) CP_ASYNC_16(dB0 + s + j * 16, pb + j * 8);
        CP_ASYNC_COMMIT();
    };

    // ldmatrix lane addressing
    const int t = lane >> 3, r8 = lane & 7;
    const uint32_t aOff = (uint32_t)(wm * 64 + (t & 1) * 8 + r8) * PA3 + ((t >> 1) * 8) * 2;
    const uint32_t bOff = TA3 + (uint32_t)(wn * 32 + (t >> 1) * 8 + r8) * PA3 + ((t & 1) * 8) * 2;

    float acc[4][4][4];
    #pragma unroll
    for (int i = 0; i < 4; i++)
        #pragma unroll
        for (int j = 0; j < 4; j++)
            #pragma unroll
            for (int k = 0; k < 4; k++) acc[i][j][k] = 0.f;

    issue(0);
    issue(1);

    for (int kc = 0; kc < NCHUNK; kc++) {
        if (kc < NCHUNK - 1) { CP_ASYNC_WAIT1(); } else { CP_ASYNC_WAIT0(); }
        __syncthreads();
        if (kc + 2 < NCHUNK) issue(kc + 2);

        const uint32_t st = sb + (kc % NSTAGE) * STG3;

        #pragma unroll
        for (int ks = 0; ks < 4; ks++) {
            uint32_t af[4][4], bf2[4][2];
            #pragma unroll
            for (int mt = 0; mt < 4; mt++)
                LDSM_X4(af[mt][0], af[mt][1], af[mt][2], af[mt][3],
                        st + aOff + (uint32_t)mt * 16 * PA3 + ks * 32);
            #pragma unroll
            for (int np = 0; np < 2; np++)
                LDSM_X4(bf2[np * 2][0], bf2[np * 2][1], bf2[np * 2 + 1][0], bf2[np * 2 + 1][1],
                        st + bOff + (uint32_t)np * 16 * PA3 + ks * 32);
            #pragma unroll
            for (int mt = 0; mt < 4; mt++)
                #pragma unroll
                for (int nt = 0; nt < 4; nt++)
                    mma_f16(acc[mt][nt], af[mt], bf2[nt]);
        }
    }

    // Epilogue: out += d_n * acc  via vector reductions (no return wait)
    #pragma unroll
    for (int mt = 0; mt < 4; mt++) {
        const int gr0 = b * NN + rowStart + wm * 64 + mt * 16 + g;
        const float d0 = g_dinv[gr0];
        const float d1 = g_dinv[gr0 + 8];
        float* o0 = out + (size_t)gr0 * FF + wn * 32 + tig * 2;
        float* o1 = o0 + (size_t)8 * FF;
        #pragma unroll
        for (int nt = 0; nt < 4; nt++) {
            RED_ADD_V2(o0 + nt * 8, d0 * acc[mt][nt][0], d0 * acc[mt][nt][1]);
            RED_ADD_V2(o1 + nt * 8, d1 * acc[mt][nt][2], d1 * acc[mt][nt][3]);
        }
    }
}

// ---------------------------------------------------------------------------
// kernel_launch
// ---------------------------------------------------------------------------
extern "C" void kernel_launch(void* const* d_in, const int* in_sizes, int n_in,
                              void* d_out, int out_size) {
    const float* X = (const float*)d_in[0];   // [16,1024,128]
    const float* A = (const float*)d_in[1];   // [16,1024,1024]
    const float* W = (const float*)d_in[2];   // [128,128]
    float* out = (float*)d_out;               // [16,1024,128]

    cudaFuncSetAttribute(gemm_xw_t, cudaFuncAttributeMaxDynamicSharedMemorySize, SMEM2);
    cudaFuncSetAttribute(gemm_mma, cudaFuncAttributeMaxDynamicSharedMemorySize, SMEM3);

    // 1) dinv = rsqrt(rowsum(A)+1)  +  Ah = fp16(A)  +  zero out (fused)
    deg_kernel<<<GTOT / 16, 256>>>(A, out);

    // 2) YsT_h = fp16(d_g * (X @ W)^T), 256 CTAs (2 f-tiles x 128 g-tiles)
    {
        dim3 grid(GTOT / 128, 2);
        gemm_xw_t<<<grid, 256, SMEM2>>>(X, W, A);
    }

    // 3) out += d_n * ((A+I) @ Ysd)  via 2-way K-split ldmatrix + fp16 mma.sync
    {
        dim3 grid(NN / 128, BATCH, KSPLIT);
        gemm_mma<<<grid, 256, SMEM3>>>(out);
    }
}